// round 6
// baseline (speedup 1.0000x reference)
#include <cuda_runtime.h>
#include <cuda_bf16.h>
#include <cstdint>

// Problem dims
#define BB 2
#define TT 2048
#define HH 16
#define DD 64
#define EE 1024   // HH*DD
#define OO 1024

// Scratch (device globals)
__device__ float g_q[(size_t)BB * TT * EE];
__device__ float g_k[(size_t)BB * TT * EE];
__device__ float g_v[(size_t)BB * TT * EE];
__device__ float g_mh[(size_t)BB * TT * EE];
__device__ float g_vt[(size_t)BB * TT * EE];          // V transposed: [b][h][d][m]
__device__ float g_pkt[(size_t)EE * OO];              // proj kernel transposed: [o][k]
__device__ float g_rowsum[(size_t)BB * HH * TT];      // softmax row sums (then inverses)
__device__ float g_out_scratch[(size_t)BB * TT * OO];
__device__ float g_attn_scratch[(size_t)BB * HH * TT * TT];

// ---------------------------------------------------------------------------
// mma.sync m16n8k16 bf16 (baseline PTX, works at compute_103)
// ---------------------------------------------------------------------------
__device__ __forceinline__ void mma16816(float* c, const uint32_t* a, const uint32_t* b) {
    asm volatile(
        "mma.sync.aligned.m16n8k16.row.col.f32.bf16.bf16.f32 "
        "{%0,%1,%2,%3}, {%4,%5,%6,%7}, {%8,%9}, {%0,%1,%2,%3};"
        : "+f"(c[0]), "+f"(c[1]), "+f"(c[2]), "+f"(c[3])
        : "r"(a[0]), "r"(a[1]), "r"(a[2]), "r"(a[3]), "r"(b[0]), "r"(b[1]));
}

// ---------------------------------------------------------------------------
// Tensor-core GEMM via mma.sync: C[M,N] = alpha * A[M,K] * B[N,K]^T (+ bias)
// fp32 inputs split on the fly into bf16 (hi,lo); 3-term compensation.
// CTA tile 256 x NTILE, K-step 32. 256 threads = 8 warps (4m x 2n).
// MODE 0: plain epilogue (alpha*acc + bias)
// MODE 1: epilogue writes exp(alpha*acc), atomicAdds per-row sums into rowsum
// MODE 2: A-staging multiplies by rowsum[row] (holds 1/sum) and writes the
//         normalized value back to AW (attention output); plain epilogue.
// ---------------------------------------------------------------------------
template <int NTILE, int MODE>
__global__ __launch_bounds__(256, 1) void mma_gemm(
    const float* __restrict__ A, int lda, int zdiv,
    long long sA1, long long sA2,
    const float* __restrict__ Bm, int ldb,
    long long sB1, long long sB2,
    float* __restrict__ C, int ldc,
    long long sC1, long long sC2,
    int K, float alpha, const float* __restrict__ bias,
    float* rowsum, float* AW)
{
    constexpr int KS   = 32;           // k per stage (bf16)
    constexpr int WROW = 20;           // 32-bit words per smem row (40 bf16, padded)
    constexpr int NI   = NTILE / 16;   // n-fragments per warp
    constexpr int NLOOP = (2048 + NTILE * 8) / 256;

    extern __shared__ char smem[];
    uint32_t* AwH = (uint32_t*)smem;
    uint32_t* AwL = AwH + 256 * WROW;
    uint32_t* BwH = AwL + 256 * WROW;
    uint32_t* BwL = BwH + NTILE * WROW;

    const int z = blockIdx.z;
    const int z1 = z / zdiv, z2 = z % zdiv;
    A  += (long long)z1 * sA1 + (long long)z2 * sA2;
    Bm += (long long)z1 * sB1 + (long long)z2 * sB2;
    C  += (long long)z1 * sC1 + (long long)z2 * sC2;
    if (MODE == 2) AW += (long long)z1 * sA1 + (long long)z2 * sA2;
    float* rowsumz = rowsum ? rowsum + (long long)z * TT : nullptr;

    const int m0 = blockIdx.y * 256;
    const int n0 = blockIdx.x * NTILE;

    const int tid  = threadIdx.x;
    const int warp = tid >> 5;
    const int lane = tid & 31;
    const int wm   = warp & 3;
    const int wn   = warp >> 2;
    const int g    = lane >> 2;
    const int tg   = lane & 3;

    float acc[4][NI][4];
#pragma unroll
    for (int mi = 0; mi < 4; mi++)
#pragma unroll
        for (int ni = 0; ni < NI; ni++)
#pragma unroll
            for (int r = 0; r < 4; r++) acc[mi][ni][r] = 0.f;

    for (int kb = 0; kb < K; kb += KS) {
        __syncthreads();
#pragma unroll
        for (int i = 0; i < NLOOP; i++) {
            const int idx = tid + i * 256;
            const bool isA = idx < 2048;
            const int r = isA ? (idx >> 3) : ((idx - 2048) >> 3);
            const int c = (idx & 7) * 4;
            const float* src = isA
                ? &A[(long long)(m0 + r) * lda + kb + c]
                : &Bm[(long long)(n0 + r) * ldb + kb + c];
            float4 x = *(const float4*)src;
            if (MODE == 2 && isA) {
                const float inv = rowsumz[m0 + r];   // holds 1/sum
                x.x *= inv; x.y *= inv; x.z *= inv; x.w *= inv;
                *(float4*)&AW[(long long)(m0 + r) * lda + kb + c] = x;
            }
            __nv_bfloat162 h0 = __floats2bfloat162_rn(x.x, x.y);
            __nv_bfloat162 h1 = __floats2bfloat162_rn(x.z, x.w);
            float l0 = x.x - __bfloat162float(h0.x);
            float l1 = x.y - __bfloat162float(h0.y);
            float l2 = x.z - __bfloat162float(h1.x);
            float l3 = x.w - __bfloat162float(h1.y);
            __nv_bfloat162 lo0 = __floats2bfloat162_rn(l0, l1);
            __nv_bfloat162 lo1 = __floats2bfloat162_rn(l2, l3);
            const uint32_t w = r * WROW + (c >> 1);
            uint32_t* dh = (isA ? AwH : BwH) + w;
            uint32_t* dl = (isA ? AwL : BwL) + w;
            *(uint2*)dh = make_uint2(*(uint32_t*)&h0, *(uint32_t*)&h1);
            *(uint2*)dl = make_uint2(*(uint32_t*)&lo0, *(uint32_t*)&lo1);
        }
        __syncthreads();

#pragma unroll
        for (int kk2 = 0; kk2 < 2; kk2++) {
            uint32_t bh[NI][2], bl[NI][2];
#pragma unroll
            for (int ni = 0; ni < NI; ni++) {
                const int n = wn * (NI * 8) + ni * 8 + g;
                const uint32_t w = n * WROW + kk2 * 8 + tg;
                bh[ni][0] = BwH[w];     bh[ni][1] = BwH[w + 4];
                bl[ni][0] = BwL[w];     bl[ni][1] = BwL[w + 4];
            }
#pragma unroll
            for (int mi = 0; mi < 4; mi++) {
                const int r = wm * 64 + mi * 16 + g;
                const uint32_t w = r * WROW + kk2 * 8 + tg;
                uint32_t ah[4] = {AwH[w], AwH[w + 8 * WROW], AwH[w + 4], AwH[w + 8 * WROW + 4]};
                uint32_t al[4] = {AwL[w], AwL[w + 8 * WROW], AwL[w + 4], AwL[w + 8 * WROW + 4]};
#pragma unroll
                for (int ni = 0; ni < NI; ni++) {
                    mma16816(acc[mi][ni], ah, bh[ni]);
                    mma16816(acc[mi][ni], ah, bl[ni]);
                    mma16816(acc[mi][ni], al, bh[ni]);
                }
            }
        }
    }

    // ---- epilogue ----
#pragma unroll
    for (int mi = 0; mi < 4; mi++) {
        const int r0 = m0 + wm * 64 + mi * 16 + g;
        const int r1 = r0 + 8;
        float p0 = 0.f, p1 = 0.f;
#pragma unroll
        for (int ni = 0; ni < NI; ni++) {
            const int c = n0 + wn * (NI * 8) + ni * 8 + tg * 2;
            float2 o0, o1;
            if (MODE == 1) {
                o0.x = __expf(acc[mi][ni][0] * alpha);
                o0.y = __expf(acc[mi][ni][1] * alpha);
                o1.x = __expf(acc[mi][ni][2] * alpha);
                o1.y = __expf(acc[mi][ni][3] * alpha);
                p0 += o0.x + o0.y;
                p1 += o1.x + o1.y;
            } else {
                float2 bv = make_float2(0.f, 0.f);
                if (bias) bv = *(const float2*)&bias[c];
                o0.x = acc[mi][ni][0] * alpha + bv.x;
                o0.y = acc[mi][ni][1] * alpha + bv.y;
                o1.x = acc[mi][ni][2] * alpha + bv.x;
                o1.y = acc[mi][ni][3] * alpha + bv.y;
            }
            *(float2*)&C[(long long)r0 * ldc + c] = o0;
            *(float2*)&C[(long long)r1 * ldc + c] = o1;
        }
        if (MODE == 1) {
            p0 += __shfl_xor_sync(0xffffffffu, p0, 1);
            p0 += __shfl_xor_sync(0xffffffffu, p0, 2);
            p1 += __shfl_xor_sync(0xffffffffu, p1, 1);
            p1 += __shfl_xor_sync(0xffffffffu, p1, 2);
            if (tg == 0) {
                atomicAdd(&rowsumz[r0], p0);
                atomicAdd(&rowsumz[r1], p1);
            }
        }
    }
}

// ---------------------------------------------------------------------------
// rowsum helpers
// ---------------------------------------------------------------------------
__global__ void zero_rowsum(float* rs) {
    rs[blockIdx.x * 256 + threadIdx.x] = 0.f;
}
__global__ void invert_rowsum(float* rs) {
    const int i = blockIdx.x * 256 + threadIdx.x;
    rs[i] = 1.f / rs[i];
}

// ---------------------------------------------------------------------------
// Transposes
// ---------------------------------------------------------------------------
__global__ __launch_bounds__(256) void transpose_v(const float* __restrict__ v,
                                                   float* __restrict__ vt)
{
    __shared__ float tile[32][33];
    const int z = blockIdx.z;
    const int b = z / HH, h = z % HH;
    const int m0 = blockIdx.x * 32;
    const int d0 = blockIdx.y * 32;
    const int tx = threadIdx.x & 31;
    const int ty0 = threadIdx.x >> 5;
#pragma unroll
    for (int ty = ty0; ty < 32; ty += 8)
        tile[ty][tx] = v[((long long)b * TT + m0 + ty) * EE + h * DD + d0 + tx];
    __syncthreads();
#pragma unroll
    for (int ty = ty0; ty < 32; ty += 8)
        vt[(((long long)z) * DD + d0 + ty) * TT + m0 + tx] = tile[tx][ty];
}

__global__ __launch_bounds__(256) void transpose_pk(const float* __restrict__ pk,
                                                    float* __restrict__ pkt)
{
    __shared__ float tile[32][33];
    const int k0 = blockIdx.x * 32;
    const int o0 = blockIdx.y * 32;
    const int tx = threadIdx.x & 31;
    const int ty0 = threadIdx.x >> 5;
#pragma unroll
    for (int ty = ty0; ty < 32; ty += 8)
        tile[ty][tx] = pk[(long long)(k0 + ty) * OO + o0 + tx];
    __syncthreads();
#pragma unroll
    for (int ty = ty0; ty < 32; ty += 8)
        pkt[(long long)(o0 + ty) * EE + k0 + tx] = tile[tx][ty];
}

// ---------------------------------------------------------------------------
// Launch
// ---------------------------------------------------------------------------
extern "C" void kernel_launch(void* const* d_in, const int* in_sizes, int n_in,
                              void* d_out, int out_size)
{
    const float* query = (const float*)d_in[0];
    const float* key   = (const float*)d_in[1];
    const float* value = (const float*)d_in[2];
    const float* Wq    = (const float*)d_in[3];
    const float* Wk    = (const float*)d_in[4];
    const float* Wv    = (const float*)d_in[5];
    const float* pk    = (const float*)d_in[6];
    const float* pb    = (const float*)d_in[7];

    float *qp, *kp, *vp, *mhp, *vtp, *pktp, *rsp, *outs, *attns;
    cudaGetSymbolAddress((void**)&qp,    g_q);
    cudaGetSymbolAddress((void**)&kp,    g_k);
    cudaGetSymbolAddress((void**)&vp,    g_v);
    cudaGetSymbolAddress((void**)&mhp,   g_mh);
    cudaGetSymbolAddress((void**)&vtp,   g_vt);
    cudaGetSymbolAddress((void**)&pktp,  g_pkt);
    cudaGetSymbolAddress((void**)&rsp,   g_rowsum);
    cudaGetSymbolAddress((void**)&outs,  g_out_scratch);
    cudaGetSymbolAddress((void**)&attns, g_attn_scratch);

    const long long outN  = (long long)BB * TT * OO;
    const long long attnN = (long long)BB * HH * TT * TT;

    float* outP  = (float*)d_out;
    float* attnP;
    if ((long long)out_size >= outN + attnN) {
        attnP = outP + outN;
    } else if ((long long)out_size == attnN) {
        attnP = (float*)d_out;
        outP  = outs;
    } else {
        attnP = attns;
    }

    constexpr int SMEM128 = (256 * 20 * 2 + 128 * 20 * 2) * 4;   // 61440
    constexpr int SMEM64  = (256 * 20 * 2 + 64 * 20 * 2) * 4;    // 51200
    cudaFuncSetAttribute(mma_gemm<128, 0>, cudaFuncAttributeMaxDynamicSharedMemorySize, SMEM128);
    cudaFuncSetAttribute(mma_gemm<128, 1>, cudaFuncAttributeMaxDynamicSharedMemorySize, SMEM128);
    cudaFuncSetAttribute(mma_gemm<64, 2>,  cudaFuncAttributeMaxDynamicSharedMemorySize, SMEM64);

    // 0) zero row sums
    zero_rowsum<<<(BB * HH * TT) / 256, 256>>>(rsp);

    // 1) Q/K/V projections: [B*T, E] = X @ W.T
    {
        dim3 grid(EE / 128, (BB * TT) / 256, 1);
        mma_gemm<128, 0><<<grid, 256, SMEM128>>>(query, EE, 1, 0, 0, Wq, EE, 0, 0,
                                                 qp, EE, 0, 0, EE, 1.f, nullptr, nullptr, nullptr);
        mma_gemm<128, 0><<<grid, 256, SMEM128>>>(key,   EE, 1, 0, 0, Wk, EE, 0, 0,
                                                 kp, EE, 0, 0, EE, 1.f, nullptr, nullptr, nullptr);
        mma_gemm<128, 0><<<grid, 256, SMEM128>>>(value, EE, 1, 0, 0, Wv, EE, 0, 0,
                                                 vp, EE, 0, 0, EE, 1.f, nullptr, nullptr, nullptr);
    }

    // transposes: V -> [b][h][d][m], pk -> [o][k]
    {
        dim3 gv(TT / 32, DD / 32, BB * HH);
        transpose_v<<<gv, 256>>>(vp, vtp);
        dim3 gp(EE / 32, OO / 32, 1);
        transpose_pk<<<gp, 256>>>(pk, pktp);
    }

    // 2) attn_exp = exp(0.125 * q @ k^T), row sums accumulated atomically
    {
        dim3 grid(TT / 128, TT / 256, BB * HH);
        mma_gemm<128, 1><<<grid, 256, SMEM128>>>(
            qp, EE, HH, (long long)TT * EE, DD,
            kp, EE,     (long long)TT * EE, DD,
            attnP, TT,  (long long)HH * TT * TT, (long long)TT * TT,
            DD, 0.125f, nullptr, rsp, nullptr);
    }

    // 3) invert row sums
    invert_rowsum<<<(BB * HH * TT) / 256, 256>>>(rsp);

    // 4) mh = softmax(attn) @ vT^T ; also writes normalized attn back
    {
        dim3 grid(1, TT / 256, BB * HH);
        mma_gemm<64, 2><<<grid, 256, SMEM64>>>(
            attnP, TT, HH, (long long)HH * TT * TT, (long long)TT * TT,
            vtp, TT,       (long long)HH * DD * TT, (long long)DD * TT,
            mhp, EE,       (long long)TT * EE, DD,
            TT, 1.f, nullptr, rsp, attnP);
    }

    // 5) out = mh @ pkT^T + bias
    {
        dim3 grid(OO / 128, (BB * TT) / 256, 1);
        mma_gemm<128, 0><<<grid, 256, SMEM128>>>(mhp, EE, 1, 0, 0, pktp, EE, 0, 0,
                                                 outP, OO, 0, 0, EE, 1.f, pb, nullptr, nullptr);
    }
}

// round 7
// speedup vs baseline: 1.4984x; 1.4984x over previous
#include <cuda_runtime.h>
#include <cuda_bf16.h>
#include <cstdint>

// Problem dims
#define BB 2
#define TT 2048
#define HH 16
#define DD 64
#define EE 1024   // HH*DD
#define OO 1024

// Scratch (device globals)
__device__ float g_qkv[(size_t)3 * BB * TT * EE];     // q | k | v contiguous
__device__ float g_mh[(size_t)BB * TT * EE];
__device__ float g_vt[(size_t)BB * TT * EE];          // V transposed: [b][h][d][m]
__device__ float g_pkt[(size_t)EE * OO];              // proj kernel transposed: [o][k]
__device__ float g_out_scratch[(size_t)BB * TT * OO];
__device__ float g_attn_scratch[(size_t)BB * HH * TT * TT];

// ---------------------------------------------------------------------------
// mma.sync m16n8k16 bf16 (baseline PTX, works at compute_103)
// ---------------------------------------------------------------------------
__device__ __forceinline__ void mma16816(float* c, const uint32_t* a, const uint32_t* b) {
    asm volatile(
        "mma.sync.aligned.m16n8k16.row.col.f32.bf16.bf16.f32 "
        "{%0,%1,%2,%3}, {%4,%5,%6,%7}, {%8,%9}, {%0,%1,%2,%3};"
        : "+f"(c[0]), "+f"(c[1]), "+f"(c[2]), "+f"(c[3])
        : "r"(a[0]), "r"(a[1]), "r"(a[2]), "r"(a[3]), "r"(b[0]), "r"(b[1]));
}

__device__ __forceinline__ void split_store(float4 x, uint32_t* dh, uint32_t* dl) {
    __nv_bfloat162 h0 = __floats2bfloat162_rn(x.x, x.y);
    __nv_bfloat162 h1 = __floats2bfloat162_rn(x.z, x.w);
    float l0 = x.x - __bfloat162float(h0.x);
    float l1 = x.y - __bfloat162float(h0.y);
    float l2 = x.z - __bfloat162float(h1.x);
    float l3 = x.w - __bfloat162float(h1.y);
    __nv_bfloat162 lo0 = __floats2bfloat162_rn(l0, l1);
    __nv_bfloat162 lo1 = __floats2bfloat162_rn(l2, l3);
    *(uint2*)dh = make_uint2(*(uint32_t*)&h0, *(uint32_t*)&h1);
    *(uint2*)dl = make_uint2(*(uint32_t*)&lo0, *(uint32_t*)&lo1);
}

// ---------------------------------------------------------------------------
// Double-buffered tensor-core GEMM: C[M,N] = alpha * A[M,K] * B[N,K]^T (+bias)
// fp32 -> bf16 (hi,lo) split on the fly, 3-term compensation.
// CTA tile 128 x NTILE, K-step 32, 256 threads = 8 warps.
//   NTILE=128: warps 2m x 4n (warp 64x32);  NTILE=64: warps 4m x 2n (warp 32x32)
// BATCH3=1: blockIdx.z in {0,1,2} selects (A,A1,A2)/(B,B1,B2), C += z*sC1.
// Else batched via z: offset = (z/zdiv)*s1 + (z%zdiv)*s2.
// ---------------------------------------------------------------------------
template <int NTILE, int BATCH3>
__global__ __launch_bounds__(256) void mma_gemm(
    const float* __restrict__ A, const float* __restrict__ A1q, const float* __restrict__ A2q,
    int lda, int zdiv, long long sA1, long long sA2,
    const float* __restrict__ Bm, const float* __restrict__ B1q, const float* __restrict__ B2q,
    int ldb, long long sB1, long long sB2,
    float* __restrict__ C, int ldc, long long sC1, long long sC2,
    int K, float alpha, const float* __restrict__ bias)
{
    constexpr int WROW  = 20;                 // words per smem row (40 bf16, padded)
    constexpr int ROWS  = 128 + NTILE;        // staged rows per K-slab
    constexpr int NLOOP = ROWS / 32;          // float4 groups per thread (8 or 6)
    constexpr int BUFW  = ROWS * 40;          // words per buffer (hi+lo, A+B)
    constexpr int WM    = (NTILE == 128) ? 2 : 4;
    constexpr int MI    = 128 / (WM * 16);    // 4 or 2
    constexpr int NI    = 4;                  // 4 n8-frags = 32 cols per warp
    constexpr int AHL   = 128 * WROW;         // 2560: A section size (words)
    constexpr int BOFF  = 2 * AHL;            // 5120: B hi section start
    constexpr int BHL   = NTILE * WROW;

    extern __shared__ char smem[];
    uint32_t* smw = (uint32_t*)smem;

    const int z = blockIdx.z;
    if (BATCH3) {
        A  = (z == 0) ? A  : (z == 1 ? A1q : A2q);
        Bm = (z == 0) ? Bm : (z == 1 ? B1q : B2q);
        C += (long long)z * sC1;
    } else {
        const int z1 = z / zdiv, z2 = z % zdiv;
        A  += (long long)z1 * sA1 + (long long)z2 * sA2;
        Bm += (long long)z1 * sB1 + (long long)z2 * sB2;
        C  += (long long)z1 * sC1 + (long long)z2 * sC2;
    }

    const int m0 = blockIdx.y * 128;
    const int n0 = blockIdx.x * NTILE;

    const int tid  = threadIdx.x;
    const int warp = tid >> 5;
    const int lane = tid & 31;
    const int wm   = warp % WM;
    const int wn   = warp / WM;
    const int g    = lane >> 2;
    const int tg   = lane & 3;

    float acc[MI][NI][4];
#pragma unroll
    for (int mi = 0; mi < MI; mi++)
#pragma unroll
        for (int ni = 0; ni < NI; ni++)
#pragma unroll
            for (int r = 0; r < 4; r++) acc[mi][ni][r] = 0.f;

    float4 rb[NLOOP];

    // ---- prologue: stage slab 0 into buffer 0 ----
#pragma unroll
    for (int i = 0; i < NLOOP; i++) {
        const int idx = tid + i * 256;
        const bool isA = idx < 1024;
        const int r = isA ? (idx >> 3) : ((idx - 1024) >> 3);
        const int c = (idx & 7) * 4;
        const float* src = isA ? &A[(long long)(m0 + r) * lda + c]
                               : &Bm[(long long)(n0 + r) * ldb + c];
        rb[i] = *(const float4*)src;
    }
#pragma unroll
    for (int i = 0; i < NLOOP; i++) {
        const int idx = tid + i * 256;
        const bool isA = idx < 1024;
        const int r = isA ? (idx >> 3) : ((idx - 1024) >> 3);
        const int c = (idx & 7) * 4;
        const uint32_t w = r * WROW + (c >> 1);
        uint32_t* dh = smw + (isA ? 0 : BOFF) + w;
        uint32_t* dl = dh + (isA ? AHL : BHL);
        split_store(rb[i], dh, dl);
    }
    __syncthreads();

    const int NIT = K / 32;
    int cur = 0;

    for (int it = 0; it < NIT; it++) {
        const bool more = (it + 1) < NIT;
        // ---- prefetch next slab into registers ----
        if (more) {
            const int kb = (it + 1) * 32;
#pragma unroll
            for (int i = 0; i < NLOOP; i++) {
                const int idx = tid + i * 256;
                const bool isA = idx < 1024;
                const int r = isA ? (idx >> 3) : ((idx - 1024) >> 3);
                const int c = (idx & 7) * 4;
                const float* src = isA ? &A[(long long)(m0 + r) * lda + kb + c]
                                       : &Bm[(long long)(n0 + r) * ldb + kb + c];
                rb[i] = *(const float4*)src;
            }
        }

        // ---- MMA from buffer cur ----
        {
            uint32_t* base = smw + cur * BUFW;
            uint32_t* AwH = base;
            uint32_t* AwL = base + AHL;
            uint32_t* BwH = base + BOFF;
            uint32_t* BwL = BwH + BHL;
#pragma unroll
            for (int kk2 = 0; kk2 < 2; kk2++) {
                uint32_t bh[NI][2], bl[NI][2];
#pragma unroll
                for (int ni = 0; ni < NI; ni++) {
                    const int n = wn * 32 + ni * 8 + g;
                    const uint32_t w = n * WROW + kk2 * 8 + tg;
                    bh[ni][0] = BwH[w];  bh[ni][1] = BwH[w + 4];
                    bl[ni][0] = BwL[w];  bl[ni][1] = BwL[w + 4];
                }
#pragma unroll
                for (int mi = 0; mi < MI; mi++) {
                    const int r = wm * (MI * 16) + mi * 16 + g;
                    const uint32_t w = r * WROW + kk2 * 8 + tg;
                    uint32_t ah[4] = {AwH[w], AwH[w + 8 * WROW], AwH[w + 4], AwH[w + 8 * WROW + 4]};
                    uint32_t al[4] = {AwL[w], AwL[w + 8 * WROW], AwL[w + 4], AwL[w + 8 * WROW + 4]};
#pragma unroll
                    for (int ni = 0; ni < NI; ni++) {
                        mma16816(acc[mi][ni], ah, bh[ni]);
                        mma16816(acc[mi][ni], ah, bl[ni]);
                        mma16816(acc[mi][ni], al, bh[ni]);
                    }
                }
            }
        }

        // ---- convert + store next slab into other buffer ----
        if (more) {
            uint32_t* base = smw + (cur ^ 1) * BUFW;
#pragma unroll
            for (int i = 0; i < NLOOP; i++) {
                const int idx = tid + i * 256;
                const bool isA = idx < 1024;
                const int r = isA ? (idx >> 3) : ((idx - 1024) >> 3);
                const int c = (idx & 7) * 4;
                const uint32_t w = r * WROW + (c >> 1);
                uint32_t* dh = base + (isA ? 0 : BOFF) + w;
                uint32_t* dl = dh + (isA ? AHL : BHL);
                split_store(rb[i], dh, dl);
            }
            __syncthreads();
        }
        cur ^= 1;
    }

    // ---- epilogue ----
#pragma unroll
    for (int mi = 0; mi < MI; mi++) {
        const int r0 = m0 + wm * (MI * 16) + mi * 16 + g;
        const int r1 = r0 + 8;
#pragma unroll
        for (int ni = 0; ni < NI; ni++) {
            const int c = n0 + wn * 32 + ni * 8 + tg * 2;
            float2 bv = make_float2(0.f, 0.f);
            if (bias) bv = *(const float2*)&bias[c];
            float2 o0, o1;
            o0.x = acc[mi][ni][0] * alpha + bv.x;
            o0.y = acc[mi][ni][1] * alpha + bv.y;
            o1.x = acc[mi][ni][2] * alpha + bv.x;
            o1.y = acc[mi][ni][3] * alpha + bv.y;
            *(float2*)&C[(long long)r0 * ldc + c] = o0;
            *(float2*)&C[(long long)r1 * ldc + c] = o1;
        }
    }
}

// ---------------------------------------------------------------------------
// Transposes
// ---------------------------------------------------------------------------
__global__ __launch_bounds__(256) void transpose_v(const float* __restrict__ v,
                                                   float* __restrict__ vt)
{
    __shared__ float tile[32][33];
    const int z = blockIdx.z;
    const int b = z / HH, h = z % HH;
    const int m0 = blockIdx.x * 32;
    const int d0 = blockIdx.y * 32;
    const int tx = threadIdx.x & 31;
    const int ty0 = threadIdx.x >> 5;
#pragma unroll
    for (int ty = ty0; ty < 32; ty += 8)
        tile[ty][tx] = v[((long long)b * TT + m0 + ty) * EE + h * DD + d0 + tx];
    __syncthreads();
#pragma unroll
    for (int ty = ty0; ty < 32; ty += 8)
        vt[(((long long)z) * DD + d0 + ty) * TT + m0 + tx] = tile[tx][ty];
}

__global__ __launch_bounds__(256) void transpose_pk(const float* __restrict__ pk,
                                                    float* __restrict__ pkt)
{
    __shared__ float tile[32][33];
    const int k0 = blockIdx.x * 32;
    const int o0 = blockIdx.y * 32;
    const int tx = threadIdx.x & 31;
    const int ty0 = threadIdx.x >> 5;
#pragma unroll
    for (int ty = ty0; ty < 32; ty += 8)
        tile[ty][tx] = pk[(long long)(k0 + ty) * OO + o0 + tx];
    __syncthreads();
#pragma unroll
    for (int ty = ty0; ty < 32; ty += 8)
        pkt[(long long)(o0 + ty) * EE + k0 + tx] = tile[tx][ty];
}

// ---------------------------------------------------------------------------
// Row softmax, in place. One block (256 threads) per row of length TT=2048.
// ---------------------------------------------------------------------------
__global__ __launch_bounds__(256) void softmax_rows(float* __restrict__ attn)
{
    __shared__ float red[256];
    const long long row = blockIdx.x;
    float4* p4 = (float4*)(attn + row * (long long)TT);
    const int t = threadIdx.x;

    float4 a = p4[t];
    float4 b = p4[t + 256];

    float m = fmaxf(fmaxf(fmaxf(a.x, a.y), fmaxf(a.z, a.w)),
                    fmaxf(fmaxf(b.x, b.y), fmaxf(b.z, b.w)));
    red[t] = m;
    __syncthreads();
#pragma unroll
    for (int s = 128; s > 0; s >>= 1) {
        if (t < s) red[t] = fmaxf(red[t], red[t + s]);
        __syncthreads();
    }
    m = red[0];
    __syncthreads();

    a.x = __expf(a.x - m); a.y = __expf(a.y - m);
    a.z = __expf(a.z - m); a.w = __expf(a.w - m);
    b.x = __expf(b.x - m); b.y = __expf(b.y - m);
    b.z = __expf(b.z - m); b.w = __expf(b.w - m);

    float sum = a.x + a.y + a.z + a.w + b.x + b.y + b.z + b.w;
    red[t] = sum;
    __syncthreads();
#pragma unroll
    for (int s = 128; s > 0; s >>= 1) {
        if (t < s) red[t] += red[t + s];
        __syncthreads();
    }
    const float inv = 1.f / red[0];

    a.x *= inv; a.y *= inv; a.z *= inv; a.w *= inv;
    b.x *= inv; b.y *= inv; b.z *= inv; b.w *= inv;
    p4[t] = a;
    p4[t + 256] = b;
}

// ---------------------------------------------------------------------------
// Launch
// ---------------------------------------------------------------------------
extern "C" void kernel_launch(void* const* d_in, const int* in_sizes, int n_in,
                              void* d_out, int out_size)
{
    const float* query = (const float*)d_in[0];
    const float* key   = (const float*)d_in[1];
    const float* value = (const float*)d_in[2];
    const float* Wq    = (const float*)d_in[3];
    const float* Wk    = (const float*)d_in[4];
    const float* Wv    = (const float*)d_in[5];
    const float* pk    = (const float*)d_in[6];
    const float* pb    = (const float*)d_in[7];

    float *qkvp, *mhp, *vtp, *pktp, *outs, *attns;
    cudaGetSymbolAddress((void**)&qkvp,  g_qkv);
    cudaGetSymbolAddress((void**)&mhp,   g_mh);
    cudaGetSymbolAddress((void**)&vtp,   g_vt);
    cudaGetSymbolAddress((void**)&pktp,  g_pkt);
    cudaGetSymbolAddress((void**)&outs,  g_out_scratch);
    cudaGetSymbolAddress((void**)&attns, g_attn_scratch);

    const long long qkvN = (long long)BB * TT * EE;
    float* qp = qkvp;
    float* kp = qkvp + qkvN;
    float* vp = qkvp + 2 * qkvN;

    const long long outN  = (long long)BB * TT * OO;
    const long long attnN = (long long)BB * HH * TT * TT;

    float* outP  = (float*)d_out;
    float* attnP;
    if ((long long)out_size >= outN + attnN) {
        attnP = outP + outN;
    } else if ((long long)out_size == attnN) {
        attnP = (float*)d_out;
        outP  = outs;
    } else {
        attnP = attns;
    }

    constexpr int SMEM128 = 2 * (128 + 128) * 40 * 4;  // 81920
    constexpr int SMEM64  = 2 * (128 + 64) * 40 * 4;   // 61440
    cudaFuncSetAttribute(mma_gemm<128, 1>, cudaFuncAttributeMaxDynamicSharedMemorySize, SMEM128);
    cudaFuncSetAttribute(mma_gemm<128, 0>, cudaFuncAttributeMaxDynamicSharedMemorySize, SMEM128);
    cudaFuncSetAttribute(mma_gemm<64, 0>,  cudaFuncAttributeMaxDynamicSharedMemorySize, SMEM64);

    // 1) Q/K/V projections, batched over z = 0,1,2
    {
        dim3 grid(EE / 128, (BB * TT) / 128, 3);
        mma_gemm<128, 1><<<grid, 256, SMEM128>>>(
            query, key, value, EE, 1, 0, 0,
            Wq, Wk, Wv, EE, 0, 0,
            qkvp, EE, qkvN, 0,
            EE, 1.f, nullptr);
    }

    // transposes: V -> [b][h][d][m], pk -> [o][k]
    {
        dim3 gv(TT / 32, DD / 32, BB * HH);
        transpose_v<<<gv, 256>>>(vp, vtp);
        dim3 gp(EE / 32, OO / 32, 1);
        transpose_pk<<<gp, 256>>>(pk, pktp);
    }

    // 2) logits = 0.125 * q @ k^T (per b,h)
    {
        dim3 grid(TT / 128, TT / 128, BB * HH);
        mma_gemm<128, 0><<<grid, 256, SMEM128>>>(
            qp, nullptr, nullptr, EE, HH, (long long)TT * EE, DD,
            kp, nullptr, nullptr, EE,     (long long)TT * EE, DD,
            attnP, TT, (long long)HH * TT * TT, (long long)TT * TT,
            DD, 0.125f, nullptr);
    }

    // 3) softmax
    softmax_rows<<<BB * HH * TT, 256>>>(attnP);

    // 4) mh = attn @ vT^T   (N = 64)
    {
        dim3 grid(1, TT / 128, BB * HH);
        mma_gemm<64, 0><<<grid, 256, SMEM64>>>(
            attnP, nullptr, nullptr, TT, HH, (long long)HH * TT * TT, (long long)TT * TT,
            vtp, nullptr, nullptr, TT, (long long)HH * DD * TT, (long long)DD * TT,
            mhp, EE, (long long)TT * EE, DD,
            TT, 1.f, nullptr);
    }

    // 5) out = mh @ pkT^T + bias
    {
        dim3 grid(OO / 128, (BB * TT) / 128, 1);
        mma_gemm<128, 0><<<grid, 256, SMEM128>>>(
            mhp, nullptr, nullptr, EE, 1, 0, 0,
            pktp, nullptr, nullptr, EE, 0, 0,
            outP, OO, 0, 0, EE, 1.f, pb);
    }
}

// round 8
// speedup vs baseline: 1.5488x; 1.0336x over previous
#include <cuda_runtime.h>
#include <cuda_bf16.h>
#include <cstdint>

// Problem dims
#define BB 2
#define TT 2048
#define HH 16
#define DD 64
#define EE 1024   // HH*DD
#define OO 1024

// Scratch (device globals)
__device__ float g_qkv[(size_t)3 * BB * TT * EE];     // q | k | v contiguous
__device__ float g_mh[(size_t)BB * TT * EE];
__device__ float g_vt[(size_t)BB * TT * EE];          // V transposed: [b][h][d][m]
__device__ float g_pkt[(size_t)EE * OO];              // proj kernel transposed: [o][k]
__device__ float g_rowsum[(size_t)BB * HH * TT];      // exp row sums -> inverses
__device__ float g_out_scratch[(size_t)BB * TT * OO];
__device__ float g_attn_scratch[(size_t)BB * HH * TT * TT];

// ---------------------------------------------------------------------------
// mma.sync m16n8k16 bf16 (baseline PTX, works at compute_103)
// ---------------------------------------------------------------------------
__device__ __forceinline__ void mma16816(float* c, const uint32_t* a, const uint32_t* b) {
    asm volatile(
        "mma.sync.aligned.m16n8k16.row.col.f32.bf16.bf16.f32 "
        "{%0,%1,%2,%3}, {%4,%5,%6,%7}, {%8,%9}, {%0,%1,%2,%3};"
        : "+f"(c[0]), "+f"(c[1]), "+f"(c[2]), "+f"(c[3])
        : "r"(a[0]), "r"(a[1]), "r"(a[2]), "r"(a[3]), "r"(b[0]), "r"(b[1]));
}

__device__ __forceinline__ void split_store(float4 x, uint32_t* dh, uint32_t* dl) {
    __nv_bfloat162 h0 = __floats2bfloat162_rn(x.x, x.y);
    __nv_bfloat162 h1 = __floats2bfloat162_rn(x.z, x.w);
    float l0 = x.x - __bfloat162float(h0.x);
    float l1 = x.y - __bfloat162float(h0.y);
    float l2 = x.z - __bfloat162float(h1.x);
    float l3 = x.w - __bfloat162float(h1.y);
    __nv_bfloat162 lo0 = __floats2bfloat162_rn(l0, l1);
    __nv_bfloat162 lo1 = __floats2bfloat162_rn(l2, l3);
    *(uint2*)dh = make_uint2(*(uint32_t*)&h0, *(uint32_t*)&h1);
    *(uint2*)dl = make_uint2(*(uint32_t*)&lo0, *(uint32_t*)&lo1);
}

// ---------------------------------------------------------------------------
// Double-buffered tensor-core GEMM: C[M,N] = alpha * A[M,K] * B[N,K]^T (+bias)
// fp32 -> bf16 (hi,lo) split on the fly, 3-term compensation.
// CTA tile 128 x NTILE, K-step 32, 256 threads = 8 warps.
// MODE 0: plain epilogue.
// MODE 1: epilogue writes exp(alpha*acc); per-row sums atomicAdd'ed into rowsum.
// MODE 2: A-staging scales rows by rowsum (holds 1/sum, reg-cached) and writes
//         the normalized values back to AW; plain epilogue.
// BATCH3=1: blockIdx.z selects (A,A1,A2)/(B,B1,B2), C += z*sC1.
// ---------------------------------------------------------------------------
template <int NTILE, int BATCH3, int MODE>
__global__ __launch_bounds__(256) void mma_gemm(
    const float* __restrict__ A, const float* __restrict__ A1q, const float* __restrict__ A2q,
    int lda, int zdiv, long long sA1, long long sA2,
    const float* __restrict__ Bm, const float* __restrict__ B1q, const float* __restrict__ B2q,
    int ldb, long long sB1, long long sB2,
    float* __restrict__ C, int ldc, long long sC1, long long sC2,
    int K, float alpha, const float* __restrict__ bias,
    float* rowsum, float* AW)
{
    constexpr int WROW  = 20;                 // words per smem row (40 bf16, padded)
    constexpr int ROWS  = 128 + NTILE;
    constexpr int NLOOP = ROWS / 32;
    constexpr int BUFW  = ROWS * 40;
    constexpr int WM    = (NTILE == 128) ? 2 : 4;
    constexpr int MI    = 128 / (WM * 16);
    constexpr int NI    = 4;
    constexpr int AHL   = 128 * WROW;
    constexpr int BOFF  = 2 * AHL;
    constexpr int BHL   = NTILE * WROW;

    extern __shared__ char smem[];
    uint32_t* smw = (uint32_t*)smem;

    const int z = blockIdx.z;
    if (BATCH3) {
        A  = (z == 0) ? A  : (z == 1 ? A1q : A2q);
        Bm = (z == 0) ? Bm : (z == 1 ? B1q : B2q);
        C += (long long)z * sC1;
    } else {
        const int z1 = z / zdiv, z2 = z % zdiv;
        A  += (long long)z1 * sA1 + (long long)z2 * sA2;
        Bm += (long long)z1 * sB1 + (long long)z2 * sB2;
        C  += (long long)z1 * sC1 + (long long)z2 * sC2;
        if (MODE == 2) AW += (long long)z1 * sA1 + (long long)z2 * sA2;
    }
    float* rowsumz = (MODE != 0) ? rowsum + (long long)z * TT : nullptr;

    const int m0 = blockIdx.y * 128;
    const int n0 = blockIdx.x * NTILE;

    const int tid  = threadIdx.x;
    const int warp = tid >> 5;
    const int lane = tid & 31;
    const int wm   = warp % WM;
    const int wn   = warp / WM;
    const int g    = lane >> 2;
    const int tg   = lane & 3;

    // MODE 2: cache 1/rowsum for this thread's 4 staged A rows
    float invc[4] = {1.f, 1.f, 1.f, 1.f};
    if (MODE == 2) {
#pragma unroll
        for (int i = 0; i < 4; i++)
            invc[i] = rowsumz[m0 + (tid >> 3) + i * 32];
    }

    float acc[MI][NI][4];
#pragma unroll
    for (int mi = 0; mi < MI; mi++)
#pragma unroll
        for (int ni = 0; ni < NI; ni++)
#pragma unroll
            for (int r = 0; r < 4; r++) acc[mi][ni][r] = 0.f;

    float4 rb[NLOOP];

    // ---- prologue: load + convert slab 0 into buffer 0 ----
#pragma unroll
    for (int i = 0; i < NLOOP; i++) {
        const int idx = tid + i * 256;
        const bool isA = idx < 1024;
        const int r = isA ? (idx >> 3) : ((idx - 1024) >> 3);
        const int c = (idx & 7) * 4;
        const float* src = isA ? &A[(long long)(m0 + r) * lda + c]
                               : &Bm[(long long)(n0 + r) * ldb + c];
        rb[i] = *(const float4*)src;
    }
#pragma unroll
    for (int i = 0; i < NLOOP; i++) {
        const int idx = tid + i * 256;
        const bool isA = idx < 1024;
        const int r = isA ? (idx >> 3) : ((idx - 1024) >> 3);
        const int c = (idx & 7) * 4;
        float4 x = rb[i];
        if (MODE == 2 && isA) {
            x.x *= invc[i]; x.y *= invc[i]; x.z *= invc[i]; x.w *= invc[i];
            *(float4*)&AW[(long long)(m0 + r) * lda + c] = x;
        }
        const uint32_t w = r * WROW + (c >> 1);
        uint32_t* dh = smw + (isA ? 0 : BOFF) + w;
        uint32_t* dl = dh + (isA ? AHL : BHL);
        split_store(x, dh, dl);
    }
    __syncthreads();

    const int NIT = K / 32;
    int cur = 0;

    for (int it = 0; it < NIT; it++) {
        const bool more = (it + 1) < NIT;
        const int kbn = (it + 1) * 32;
        // ---- prefetch next slab into registers ----
        if (more) {
#pragma unroll
            for (int i = 0; i < NLOOP; i++) {
                const int idx = tid + i * 256;
                const bool isA = idx < 1024;
                const int r = isA ? (idx >> 3) : ((idx - 1024) >> 3);
                const int c = (idx & 7) * 4;
                const float* src = isA ? &A[(long long)(m0 + r) * lda + kbn + c]
                                       : &Bm[(long long)(n0 + r) * ldb + kbn + c];
                rb[i] = *(const float4*)src;
            }
        }

        // ---- MMA from buffer cur ----
        {
            uint32_t* base = smw + cur * BUFW;
            uint32_t* AwH = base;
            uint32_t* AwL = base + AHL;
            uint32_t* BwH = base + BOFF;
            uint32_t* BwL = BwH + BHL;
#pragma unroll
            for (int kk2 = 0; kk2 < 2; kk2++) {
                uint32_t bh[NI][2], bl[NI][2];
#pragma unroll
                for (int ni = 0; ni < NI; ni++) {
                    const int n = wn * 32 + ni * 8 + g;
                    const uint32_t w = n * WROW + kk2 * 8 + tg;
                    bh[ni][0] = BwH[w];  bh[ni][1] = BwH[w + 4];
                    bl[ni][0] = BwL[w];  bl[ni][1] = BwL[w + 4];
                }
#pragma unroll
                for (int mi = 0; mi < MI; mi++) {
                    const int r = wm * (MI * 16) + mi * 16 + g;
                    const uint32_t w = r * WROW + kk2 * 8 + tg;
                    uint32_t ah[4] = {AwH[w], AwH[w + 8 * WROW], AwH[w + 4], AwH[w + 8 * WROW + 4]};
                    uint32_t al[4] = {AwL[w], AwL[w + 8 * WROW], AwL[w + 4], AwL[w + 8 * WROW + 4]};
#pragma unroll
                    for (int ni = 0; ni < NI; ni++) {
                        mma16816(acc[mi][ni], ah, bh[ni]);
                        mma16816(acc[mi][ni], ah, bl[ni]);
                        mma16816(acc[mi][ni], al, bh[ni]);
                    }
                }
            }
        }

        // ---- convert + store next slab into other buffer ----
        if (more) {
            uint32_t* base = smw + (cur ^ 1) * BUFW;
#pragma unroll
            for (int i = 0; i < NLOOP; i++) {
                const int idx = tid + i * 256;
                const bool isA = idx < 1024;
                const int r = isA ? (idx >> 3) : ((idx - 1024) >> 3);
                const int c = (idx & 7) * 4;
                float4 x = rb[i];
                if (MODE == 2 && isA) {
                    x.x *= invc[i]; x.y *= invc[i]; x.z *= invc[i]; x.w *= invc[i];
                    *(float4*)&AW[(long long)(m0 + r) * lda + kbn + c] = x;
                }
                const uint32_t w = r * WROW + (c >> 1);
                uint32_t* dh = base + (isA ? 0 : BOFF) + w;
                uint32_t* dl = dh + (isA ? AHL : BHL);
                split_store(x, dh, dl);
            }
            __syncthreads();
        }
        cur ^= 1;
    }

    // ---- epilogue ----
#pragma unroll
    for (int mi = 0; mi < MI; mi++) {
        const int r0 = m0 + wm * (MI * 16) + mi * 16 + g;
        const int r1 = r0 + 8;
        float p0 = 0.f, p1 = 0.f;
#pragma unroll
        for (int ni = 0; ni < NI; ni++) {
            const int c = n0 + wn * 32 + ni * 8 + tg * 2;
            float2 o0, o1;
            if (MODE == 1) {
                o0.x = __expf(acc[mi][ni][0] * alpha);
                o0.y = __expf(acc[mi][ni][1] * alpha);
                o1.x = __expf(acc[mi][ni][2] * alpha);
                o1.y = __expf(acc[mi][ni][3] * alpha);
                p0 += o0.x + o0.y;
                p1 += o1.x + o1.y;
            } else {
                float2 bv = make_float2(0.f, 0.f);
                if (bias) bv = *(const float2*)&bias[c];
                o0.x = acc[mi][ni][0] * alpha + bv.x;
                o0.y = acc[mi][ni][1] * alpha + bv.y;
                o1.x = acc[mi][ni][2] * alpha + bv.x;
                o1.y = acc[mi][ni][3] * alpha + bv.y;
            }
            *(float2*)&C[(long long)r0 * ldc + c] = o0;
            *(float2*)&C[(long long)r1 * ldc + c] = o1;
        }
        if (MODE == 1) {
            p0 += __shfl_xor_sync(0xffffffffu, p0, 1);
            p0 += __shfl_xor_sync(0xffffffffu, p0, 2);
            p1 += __shfl_xor_sync(0xffffffffu, p1, 1);
            p1 += __shfl_xor_sync(0xffffffffu, p1, 2);
            if (tg == 0) {
                atomicAdd(&rowsumz[r0], p0);
                atomicAdd(&rowsumz[r1], p1);
            }
        }
    }
}

// ---------------------------------------------------------------------------
// rowsum helpers
// ---------------------------------------------------------------------------
__global__ void zero_rowsum(float* rs) {
    rs[blockIdx.x * 256 + threadIdx.x] = 0.f;
}
__global__ void invert_rowsum(float* rs) {
    const int i = blockIdx.x * 256 + threadIdx.x;
    rs[i] = 1.f / rs[i];
}

// ---------------------------------------------------------------------------
// Transposes
// ---------------------------------------------------------------------------
__global__ __launch_bounds__(256) void transpose_v(const float* __restrict__ v,
                                                   float* __restrict__ vt)
{
    __shared__ float tile[32][33];
    const int z = blockIdx.z;
    const int b = z / HH, h = z % HH;
    const int m0 = blockIdx.x * 32;
    const int d0 = blockIdx.y * 32;
    const int tx = threadIdx.x & 31;
    const int ty0 = threadIdx.x >> 5;
#pragma unroll
    for (int ty = ty0; ty < 32; ty += 8)
        tile[ty][tx] = v[((long long)b * TT + m0 + ty) * EE + h * DD + d0 + tx];
    __syncthreads();
#pragma unroll
    for (int ty = ty0; ty < 32; ty += 8)
        vt[(((long long)z) * DD + d0 + ty) * TT + m0 + tx] = tile[tx][ty];
}

__global__ __launch_bounds__(256) void transpose_pk(const float* __restrict__ pk,
                                                    float* __restrict__ pkt)
{
    __shared__ float tile[32][33];
    const int k0 = blockIdx.x * 32;
    const int o0 = blockIdx.y * 32;
    const int tx = threadIdx.x & 31;
    const int ty0 = threadIdx.x >> 5;
#pragma unroll
    for (int ty = ty0; ty < 32; ty += 8)
        tile[ty][tx] = pk[(long long)(k0 + ty) * OO + o0 + tx];
    __syncthreads();
#pragma unroll
    for (int ty = ty0; ty < 32; ty += 8)
        pkt[(long long)(o0 + ty) * EE + k0 + tx] = tile[tx][ty];
}

// ---------------------------------------------------------------------------
// Launch
// ---------------------------------------------------------------------------
extern "C" void kernel_launch(void* const* d_in, const int* in_sizes, int n_in,
                              void* d_out, int out_size)
{
    const float* query = (const float*)d_in[0];
    const float* key   = (const float*)d_in[1];
    const float* value = (const float*)d_in[2];
    const float* Wq    = (const float*)d_in[3];
    const float* Wk    = (const float*)d_in[4];
    const float* Wv    = (const float*)d_in[5];
    const float* pk    = (const float*)d_in[6];
    const float* pb    = (const float*)d_in[7];

    float *qkvp, *mhp, *vtp, *pktp, *rsp, *outs, *attns;
    cudaGetSymbolAddress((void**)&qkvp,  g_qkv);
    cudaGetSymbolAddress((void**)&mhp,   g_mh);
    cudaGetSymbolAddress((void**)&vtp,   g_vt);
    cudaGetSymbolAddress((void**)&pktp,  g_pkt);
    cudaGetSymbolAddress((void**)&rsp,   g_rowsum);
    cudaGetSymbolAddress((void**)&outs,  g_out_scratch);
    cudaGetSymbolAddress((void**)&attns, g_attn_scratch);

    const long long qkvN = (long long)BB * TT * EE;
    float* qp = qkvp;
    float* kp = qkvp + qkvN;
    float* vp = qkvp + 2 * qkvN;

    const long long outN  = (long long)BB * TT * OO;
    const long long attnN = (long long)BB * HH * TT * TT;

    float* outP  = (float*)d_out;
    float* attnP;
    if ((long long)out_size >= outN + attnN) {
        attnP = outP + outN;
    } else if ((long long)out_size == attnN) {
        attnP = (float*)d_out;
        outP  = outs;
    } else {
        attnP = attns;
    }

    constexpr int SMEM128 = 2 * (128 + 128) * 40 * 4;  // 81920
    constexpr int SMEM64  = 2 * (128 + 64) * 40 * 4;   // 61440
    cudaFuncSetAttribute(mma_gemm<128, 1, 0>, cudaFuncAttributeMaxDynamicSharedMemorySize, SMEM128);
    cudaFuncSetAttribute(mma_gemm<128, 0, 0>, cudaFuncAttributeMaxDynamicSharedMemorySize, SMEM128);
    cudaFuncSetAttribute(mma_gemm<128, 0, 1>, cudaFuncAttributeMaxDynamicSharedMemorySize, SMEM128);
    cudaFuncSetAttribute(mma_gemm<64, 0, 2>,  cudaFuncAttributeMaxDynamicSharedMemorySize, SMEM64);

    // 0) zero row sums (graph-replay safe)
    zero_rowsum<<<(BB * HH * TT) / 256, 256>>>(rsp);

    // 1) Q/K/V projections, batched over z = 0,1,2
    {
        dim3 grid(EE / 128, (BB * TT) / 128, 3);
        mma_gemm<128, 1, 0><<<grid, 256, SMEM128>>>(
            query, key, value, EE, 1, 0, 0,
            Wq, Wk, Wv, EE, 0, 0,
            qkvp, EE, qkvN, 0,
            EE, 1.f, nullptr, nullptr, nullptr);
    }

    // transposes: V -> [b][h][d][m], pk -> [o][k]
    {
        dim3 gv(TT / 32, DD / 32, BB * HH);
        transpose_v<<<gv, 256>>>(vp, vtp);
        dim3 gp(EE / 32, OO / 32, 1);
        transpose_pk<<<gp, 256>>>(pk, pktp);
    }

    // 2) attn = exp(0.125 * q @ k^T), row sums via atomics
    {
        dim3 grid(TT / 128, TT / 128, BB * HH);
        mma_gemm<128, 0, 1><<<grid, 256, SMEM128>>>(
            qp, nullptr, nullptr, EE, HH, (long long)TT * EE, DD,
            kp, nullptr, nullptr, EE,     (long long)TT * EE, DD,
            attnP, TT, (long long)HH * TT * TT, (long long)TT * TT,
            DD, 0.125f, nullptr, rsp, nullptr);
    }

    // 3) invert row sums
    invert_rowsum<<<(BB * HH * TT) / 256, 256>>>(rsp);

    // 4) mh = softmax(attn) @ vT^T ; normalizes attn in staging + writes it back
    {
        dim3 grid(1, TT / 128, BB * HH);
        mma_gemm<64, 0, 2><<<grid, 256, SMEM64>>>(
            attnP, nullptr, nullptr, TT, HH, (long long)HH * TT * TT, (long long)TT * TT,
            vtp, nullptr, nullptr, TT, (long long)HH * DD * TT, (long long)DD * TT,
            mhp, EE, (long long)TT * EE, DD,
            TT, 1.f, nullptr, rsp, attnP);
    }

    // 5) out = mh @ pkT^T + bias
    {
        dim3 grid(OO / 128, (BB * TT) / 128, 1);
        mma_gemm<128, 0, 0><<<grid, 256, SMEM128>>>(
            mhp, nullptr, nullptr, EE, 1, 0, 0,
            pktp, nullptr, nullptr, EE, 0, 0,
            outP, OO, 0, 0, EE, 1.f, pb, nullptr, nullptr);
    }
}

// round 9
// speedup vs baseline: 1.7089x; 1.1034x over previous
#include <cuda_runtime.h>
#include <cuda_bf16.h>
#include <cstdint>

// Problem dims
#define BB 2
#define TT 2048
#define HH 16
#define DD 64
#define EE 1024   // HH*DD
#define OO 1024

// Scratch (device globals)
__device__ float g_qkv[(size_t)3 * BB * TT * EE];     // q | k | v contiguous
__device__ float g_mh[(size_t)BB * TT * EE];
__device__ float g_vt[(size_t)BB * TT * EE];          // V transposed: [b][h][d][m]
__device__ float g_pkt[(size_t)EE * OO];              // proj kernel transposed: [o][k]
__device__ float g_rowsum[(size_t)BB * HH * TT];      // exp row sums -> inverses
__device__ float g_out_scratch[(size_t)BB * TT * OO];
__device__ float g_attn_scratch[(size_t)BB * HH * TT * TT];

// ---------------------------------------------------------------------------
// PTX helpers (baseline features only: sm_80-era, legal at compute_103)
// ---------------------------------------------------------------------------
__device__ __forceinline__ uint32_t smem_u32(const void* p) {
    uint32_t a;
    asm("{ .reg .u64 t; cvta.to.shared.u64 t, %1; cvt.u32.u64 %0, t; }" : "=r"(a) : "l"(p));
    return a;
}
#define CP_ASYNC16(dst_u32, src_ptr) \
    asm volatile("cp.async.cg.shared.global [%0], [%1], 16;" :: "r"(dst_u32), "l"(src_ptr))
#define CP_COMMIT() asm volatile("cp.async.commit_group;" ::: "memory")
#define CP_WAIT1()  asm volatile("cp.async.wait_group 1;" ::: "memory")
#define CP_WAIT0()  asm volatile("cp.async.wait_group 0;" ::: "memory")

__device__ __forceinline__ void mma16816(float* c, const uint32_t* a, const uint32_t* b) {
    asm volatile(
        "mma.sync.aligned.m16n8k16.row.col.f32.bf16.bf16.f32 "
        "{%0,%1,%2,%3}, {%4,%5,%6,%7}, {%8,%9}, {%0,%1,%2,%3};"
        : "+f"(c[0]), "+f"(c[1]), "+f"(c[2]), "+f"(c[3])
        : "r"(a[0]), "r"(a[1]), "r"(a[2]), "r"(a[3]), "r"(b[0]), "r"(b[1]));
}

__device__ __forceinline__ void split_store(float4 x, uint32_t* dh, uint32_t* dl) {
    __nv_bfloat162 h0 = __floats2bfloat162_rn(x.x, x.y);
    __nv_bfloat162 h1 = __floats2bfloat162_rn(x.z, x.w);
    float l0 = x.x - __bfloat162float(h0.x);
    float l1 = x.y - __bfloat162float(h0.y);
    float l2 = x.z - __bfloat162float(h1.x);
    float l3 = x.w - __bfloat162float(h1.y);
    __nv_bfloat162 lo0 = __floats2bfloat162_rn(l0, l1);
    __nv_bfloat162 lo1 = __floats2bfloat162_rn(l2, l3);
    *(uint2*)dh = make_uint2(*(uint32_t*)&h0, *(uint32_t*)&h1);
    *(uint2*)dl = make_uint2(*(uint32_t*)&lo0, *(uint32_t*)&lo1);
}

// ---------------------------------------------------------------------------
// cp.async double-buffered tensor-core GEMM:
//   C[M,N] = alpha * A[M,K] * B[N,K]^T (+bias)
// fp32 -> bf16 (hi,lo) split via smem, 3-term compensation.
// CTA tile 128 x NTILE, K-step 32, 256 threads = 8 warps, 2 CTAs/SM.
// MODE 0: plain epilogue.
// MODE 1: epilogue writes exp(alpha*acc); row sums atomicAdd'ed into rowsum.
// MODE 2: convert phase scales A rows by rowsum (1/sum, reg-cached) and writes
//         normalized values back to AW.
// BATCH3=1: blockIdx.z selects (A,A1,A2)/(B,B1,B2), C += z*sC1.
// ---------------------------------------------------------------------------
template <int NTILE, int BATCH3, int MODE>
__global__ __launch_bounds__(256, 2) void mma_gemm(
    const float* __restrict__ A, const float* __restrict__ A1q, const float* __restrict__ A2q,
    int lda, int zdiv, long long sA1, long long sA2,
    const float* __restrict__ Bm, const float* __restrict__ B1q, const float* __restrict__ B2q,
    int ldb, long long sB1, long long sB2,
    float* __restrict__ C, int ldc, long long sC1, long long sC2,
    int K, float alpha, const float* __restrict__ bias,
    float* rowsum, float* AW)
{
    constexpr int WROW  = 20;                 // bf16 buffer: words per row (40 bf16)
    constexpr int ROWS  = 128 + NTILE;
    constexpr int NLOOP = ROWS / 32;          // 16B groups per thread per slab
    constexpr int RAWW  = ROWS * 32;          // raw fp32 slab, words
    constexpr int WM    = (NTILE == 128) ? 2 : 4;
    constexpr int MI    = 128 / (WM * 16);
    constexpr int NI    = 4;
    constexpr int AHL   = 128 * WROW;
    constexpr int BOFF  = 2 * AHL;
    constexpr int BHL   = NTILE * WROW;

    extern __shared__ char smem[];
    float*    raw0p = (float*)smem;
    float*    raw1p = (float*)(smem + RAWW * 4);
    uint32_t* bw    = (uint32_t*)(smem + 2 * RAWW * 4);
    const uint32_t raw0a = smem_u32(raw0p);
    const uint32_t raw1a = raw0a + RAWW * 4;

    const int z = blockIdx.z;
    if (BATCH3) {
        A  = (z == 0) ? A  : (z == 1 ? A1q : A2q);
        Bm = (z == 0) ? Bm : (z == 1 ? B1q : B2q);
        C += (long long)z * sC1;
    } else {
        const int z1 = z / zdiv, z2 = z % zdiv;
        A  += (long long)z1 * sA1 + (long long)z2 * sA2;
        Bm += (long long)z1 * sB1 + (long long)z2 * sB2;
        C  += (long long)z1 * sC1 + (long long)z2 * sC2;
        if (MODE == 2) AW += (long long)z1 * sA1 + (long long)z2 * sA2;
    }
    float* rowsumz = (MODE != 0) ? rowsum + (long long)z * TT : nullptr;

    const int m0 = blockIdx.y * 128;
    const int n0 = blockIdx.x * NTILE;

    const int tid  = threadIdx.x;
    const int warp = tid >> 5;
    const int lane = tid & 31;
    const int wm   = warp % WM;
    const int wn   = warp / WM;
    const int g    = lane >> 2;
    const int tg   = lane & 3;

    // MODE 2: cache 1/rowsum for this thread's staged A rows
    float invc[4] = {1.f, 1.f, 1.f, 1.f};
    if (MODE == 2) {
#pragma unroll
        for (int i = 0; i < 4; i++)
            invc[i] = rowsumz[m0 + (tid >> 3) + i * 32];
    }

    float acc[MI][NI][4];
#pragma unroll
    for (int mi = 0; mi < MI; mi++)
#pragma unroll
        for (int ni = 0; ni < NI; ni++)
#pragma unroll
            for (int r = 0; r < 4; r++) acc[mi][ni][r] = 0.f;

    // ---- prologue: cp.async slab 0 into raw buffer 0 ----
#pragma unroll
    for (int i = 0; i < NLOOP; i++) {
        const int idx = tid + i * 256;
        const bool isA = idx < 1024;
        const int r = isA ? (idx >> 3) : ((idx - 1024) >> 3);
        const int c = (idx & 7) * 4;
        const float* src = isA ? &A[(long long)(m0 + r) * lda + c]
                               : &Bm[(long long)(n0 + r) * ldb + c];
        CP_ASYNC16(raw0a + idx * 16, src);
    }
    CP_COMMIT();

    const int NIT = K / 32;

    for (int it = 0; it < NIT; it++) {
        const bool more = (it + 1) < NIT;
        const int kbn = (it + 1) * 32;
        // ---- issue prefetch for next slab ----
        if (more) {
            const uint32_t rdst = ((it + 1) & 1) ? raw1a : raw0a;
#pragma unroll
            for (int i = 0; i < NLOOP; i++) {
                const int idx = tid + i * 256;
                const bool isA = idx < 1024;
                const int r = isA ? (idx >> 3) : ((idx - 1024) >> 3);
                const int c = (idx & 7) * 4;
                const float* src = isA ? &A[(long long)(m0 + r) * lda + kbn + c]
                                       : &Bm[(long long)(n0 + r) * ldb + kbn + c];
                CP_ASYNC16(rdst + idx * 16, src);
            }
            CP_COMMIT();
            CP_WAIT1();    // slab `it` complete (this thread's groups)
        } else {
            CP_WAIT0();
        }

        // ---- convert own groups raw -> bf16 hi/lo (+ MODE2 writeback) ----
        {
            const float* rbuf = (it & 1) ? raw1p : raw0p;
            const int kb = it * 32;
#pragma unroll
            for (int i = 0; i < NLOOP; i++) {
                const int idx = tid + i * 256;
                const bool isA = idx < 1024;
                const int r = isA ? (idx >> 3) : ((idx - 1024) >> 3);
                const int c = (idx & 7) * 4;
                float4 x = *(const float4*)(rbuf + idx * 4);
                if (MODE == 2 && isA) {
                    x.x *= invc[i]; x.y *= invc[i]; x.z *= invc[i]; x.w *= invc[i];
                    *(float4*)&AW[(long long)(m0 + r) * lda + kb + c] = x;
                }
                const uint32_t w = r * WROW + (c >> 1);
                uint32_t* dh = bw + (isA ? 0 : BOFF) + w;
                uint32_t* dl = dh + (isA ? AHL : BHL);
                split_store(x, dh, dl);
            }
        }
        __syncthreads();

        // ---- MMA from bw ----
        {
            uint32_t* AwH = bw;
            uint32_t* AwL = bw + AHL;
            uint32_t* BwH = bw + BOFF;
            uint32_t* BwL = BwH + BHL;
#pragma unroll
            for (int kk2 = 0; kk2 < 2; kk2++) {
                uint32_t bh[NI][2], bl[NI][2];
#pragma unroll
                for (int ni = 0; ni < NI; ni++) {
                    const int n = wn * 32 + ni * 8 + g;
                    const uint32_t w = n * WROW + kk2 * 8 + tg;
                    bh[ni][0] = BwH[w];  bh[ni][1] = BwH[w + 4];
                    bl[ni][0] = BwL[w];  bl[ni][1] = BwL[w + 4];
                }
#pragma unroll
                for (int mi = 0; mi < MI; mi++) {
                    const int r = wm * (MI * 16) + mi * 16 + g;
                    const uint32_t w = r * WROW + kk2 * 8 + tg;
                    uint32_t ah[4] = {AwH[w], AwH[w + 8 * WROW], AwH[w + 4], AwH[w + 8 * WROW + 4]};
                    uint32_t al[4] = {AwL[w], AwL[w + 8 * WROW], AwL[w + 4], AwL[w + 8 * WROW + 4]};
#pragma unroll
                    for (int ni = 0; ni < NI; ni++) {
                        mma16816(acc[mi][ni], ah, bh[ni]);
                        mma16816(acc[mi][ni], ah, bl[ni]);
                        mma16816(acc[mi][ni], al, bh[ni]);
                    }
                }
            }
        }
        if (more) __syncthreads();   // protect bw before next convert
    }

    // ---- epilogue ----
#pragma unroll
    for (int mi = 0; mi < MI; mi++) {
        const int r0 = m0 + wm * (MI * 16) + mi * 16 + g;
        const int r1 = r0 + 8;
        float p0 = 0.f, p1 = 0.f;
#pragma unroll
        for (int ni = 0; ni < NI; ni++) {
            const int c = n0 + wn * 32 + ni * 8 + tg * 2;
            float2 o0, o1;
            if (MODE == 1) {
                o0.x = __expf(acc[mi][ni][0] * alpha);
                o0.y = __expf(acc[mi][ni][1] * alpha);
                o1.x = __expf(acc[mi][ni][2] * alpha);
                o1.y = __expf(acc[mi][ni][3] * alpha);
                p0 += o0.x + o0.y;
                p1 += o1.x + o1.y;
            } else {
                float2 bv = make_float2(0.f, 0.f);
                if (bias) bv = *(const float2*)&bias[c];
                o0.x = acc[mi][ni][0] * alpha + bv.x;
                o0.y = acc[mi][ni][1] * alpha + bv.y;
                o1.x = acc[mi][ni][2] * alpha + bv.x;
                o1.y = acc[mi][ni][3] * alpha + bv.y;
            }
            *(float2*)&C[(long long)r0 * ldc + c] = o0;
            *(float2*)&C[(long long)r1 * ldc + c] = o1;
        }
        if (MODE == 1) {
            p0 += __shfl_xor_sync(0xffffffffu, p0, 1);
            p0 += __shfl_xor_sync(0xffffffffu, p0, 2);
            p1 += __shfl_xor_sync(0xffffffffu, p1, 1);
            p1 += __shfl_xor_sync(0xffffffffu, p1, 2);
            if (tg == 0) {
                atomicAdd(&rowsumz[r0], p0);
                atomicAdd(&rowsumz[r1], p1);
            }
        }
    }
}

// ---------------------------------------------------------------------------
// rowsum helpers
// ---------------------------------------------------------------------------
__global__ void zero_rowsum(float* rs) {
    rs[blockIdx.x * 256 + threadIdx.x] = 0.f;
}
__global__ void invert_rowsum(float* rs) {
    const int i = blockIdx.x * 256 + threadIdx.x;
    rs[i] = 1.f / rs[i];
}

// ---------------------------------------------------------------------------
// Transposes
// ---------------------------------------------------------------------------
__global__ __launch_bounds__(256) void transpose_v(const float* __restrict__ v,
                                                   float* __restrict__ vt)
{
    __shared__ float tile[32][33];
    const int z = blockIdx.z;
    const int b = z / HH, h = z % HH;
    const int m0 = blockIdx.x * 32;
    const int d0 = blockIdx.y * 32;
    const int tx = threadIdx.x & 31;
    const int ty0 = threadIdx.x >> 5;
#pragma unroll
    for (int ty = ty0; ty < 32; ty += 8)
        tile[ty][tx] = v[((long long)b * TT + m0 + ty) * EE + h * DD + d0 + tx];
    __syncthreads();
#pragma unroll
    for (int ty = ty0; ty < 32; ty += 8)
        vt[(((long long)z) * DD + d0 + ty) * TT + m0 + tx] = tile[tx][ty];
}

__global__ __launch_bounds__(256) void transpose_pk(const float* __restrict__ pk,
                                                    float* __restrict__ pkt)
{
    __shared__ float tile[32][33];
    const int k0 = blockIdx.x * 32;
    const int o0 = blockIdx.y * 32;
    const int tx = threadIdx.x & 31;
    const int ty0 = threadIdx.x >> 5;
#pragma unroll
    for (int ty = ty0; ty < 32; ty += 8)
        tile[ty][tx] = pk[(long long)(k0 + ty) * OO + o0 + tx];
    __syncthreads();
#pragma unroll
    for (int ty = ty0; ty < 32; ty += 8)
        pkt[(long long)(o0 + ty) * EE + k0 + tx] = tile[tx][ty];
}

// ---------------------------------------------------------------------------
// Launch
// ---------------------------------------------------------------------------
extern "C" void kernel_launch(void* const* d_in, const int* in_sizes, int n_in,
                              void* d_out, int out_size)
{
    const float* query = (const float*)d_in[0];
    const float* key   = (const float*)d_in[1];
    const float* value = (const float*)d_in[2];
    const float* Wq    = (const float*)d_in[3];
    const float* Wk    = (const float*)d_in[4];
    const float* Wv    = (const float*)d_in[5];
    const float* pk    = (const float*)d_in[6];
    const float* pb    = (const float*)d_in[7];

    float *qkvp, *mhp, *vtp, *pktp, *rsp, *outs, *attns;
    cudaGetSymbolAddress((void**)&qkvp,  g_qkv);
    cudaGetSymbolAddress((void**)&mhp,   g_mh);
    cudaGetSymbolAddress((void**)&vtp,   g_vt);
    cudaGetSymbolAddress((void**)&pktp,  g_pkt);
    cudaGetSymbolAddress((void**)&rsp,   g_rowsum);
    cudaGetSymbolAddress((void**)&outs,  g_out_scratch);
    cudaGetSymbolAddress((void**)&attns, g_attn_scratch);

    const long long qkvN = (long long)BB * TT * EE;
    float* qp = qkvp;
    float* kp = qkvp + qkvN;
    float* vp = qkvp + 2 * qkvN;

    const long long outN  = (long long)BB * TT * OO;
    const long long attnN = (long long)BB * HH * TT * TT;

    float* outP  = (float*)d_out;
    float* attnP;
    if ((long long)out_size >= outN + attnN) {
        attnP = outP + outN;
    } else if ((long long)out_size == attnN) {
        attnP = (float*)d_out;
        outP  = outs;
    } else {
        attnP = attns;
    }

    // smem: 2 raw fp32 slabs + 1 bf16 hi/lo buffer
    constexpr int SMEM128 = (2 * 256 * 32 + 256 * 40) * 4;  // 106496
    constexpr int SMEM64  = (2 * 192 * 32 + 192 * 40) * 4;  // 79872
    cudaFuncSetAttribute(mma_gemm<128, 1, 0>, cudaFuncAttributeMaxDynamicSharedMemorySize, SMEM128);
    cudaFuncSetAttribute(mma_gemm<128, 0, 0>, cudaFuncAttributeMaxDynamicSharedMemorySize, SMEM128);
    cudaFuncSetAttribute(mma_gemm<128, 0, 1>, cudaFuncAttributeMaxDynamicSharedMemorySize, SMEM128);
    cudaFuncSetAttribute(mma_gemm<64, 0, 2>,  cudaFuncAttributeMaxDynamicSharedMemorySize, SMEM64);

    // 0) zero row sums (graph-replay safe)
    zero_rowsum<<<(BB * HH * TT) / 256, 256>>>(rsp);

    // 1) Q/K/V projections, batched over z = 0,1,2
    {
        dim3 grid(EE / 128, (BB * TT) / 128, 3);
        mma_gemm<128, 1, 0><<<grid, 256, SMEM128>>>(
            query, key, value, EE, 1, 0, 0,
            Wq, Wk, Wv, EE, 0, 0,
            qkvp, EE, qkvN, 0,
            EE, 1.f, nullptr, nullptr, nullptr);
    }

    // transposes: V -> [b][h][d][m], pk -> [o][k]
    {
        dim3 gv(TT / 32, DD / 32, BB * HH);
        transpose_v<<<gv, 256>>>(vp, vtp);
        dim3 gp(EE / 32, OO / 32, 1);
        transpose_pk<<<gp, 256>>>(pk, pktp);
    }

    // 2) attn = exp(0.125 * q @ k^T), row sums via atomics
    {
        dim3 grid(TT / 128, TT / 128, BB * HH);
        mma_gemm<128, 0, 1><<<grid, 256, SMEM128>>>(
            qp, nullptr, nullptr, EE, HH, (long long)TT * EE, DD,
            kp, nullptr, nullptr, EE,     (long long)TT * EE, DD,
            attnP, TT, (long long)HH * TT * TT, (long long)TT * TT,
            DD, 0.125f, nullptr, rsp, nullptr);
    }

    // 3) invert row sums
    invert_rowsum<<<(BB * HH * TT) / 256, 256>>>(rsp);

    // 4) mh = softmax(attn) @ vT^T ; normalizes attn in staging + writes it back
    {
        dim3 grid(1, TT / 128, BB * HH);
        mma_gemm<64, 0, 2><<<grid, 256, SMEM64>>>(
            attnP, nullptr, nullptr, TT, HH, (long long)HH * TT * TT, (long long)TT * TT,
            vtp, nullptr, nullptr, TT, (long long)HH * DD * TT, (long long)DD * TT,
            mhp, EE, (long long)TT * EE, DD,
            TT, 1.f, nullptr, rsp, attnP);
    }

    // 5) out = mh @ pkT^T + bias
    {
        dim3 grid(OO / 128, (BB * TT) / 128, 1);
        mma_gemm<128, 0, 0><<<grid, 256, SMEM128>>>(
            mhp, nullptr, nullptr, EE, 1, 0, 0,
            pktp, nullptr, nullptr, EE, 0, 0,
            outP, OO, 0, 0, EE, 1.f, pb, nullptr, nullptr);
    }
}

// round 10
// speedup vs baseline: 1.8908x; 1.1064x over previous
#include <cuda_runtime.h>
#include <cuda_bf16.h>
#include <cstdint>

// Problem dims
#define BB 2
#define TT 2048
#define HH 16
#define DD 64
#define EE 1024   // HH*DD
#define OO 1024

// Scratch (device globals)
__device__ float g_qkv[(size_t)3 * BB * TT * EE];     // q | k | v contiguous
__device__ float g_mh[(size_t)BB * TT * EE];
__device__ float g_vt[(size_t)BB * TT * EE];          // V transposed: [b][h][d][m]
__device__ float g_pkt[(size_t)EE * OO];              // proj kernel transposed: [o][k]
__device__ float g_rowsum[(size_t)BB * HH * TT];      // exp row sums -> inverses
__device__ float g_out_scratch[(size_t)BB * TT * OO];
__device__ float g_attn_scratch[(size_t)BB * HH * TT * TT];

// ---------------------------------------------------------------------------
// PTX helpers (baseline features only: sm_80-era, legal at compute_103)
// ---------------------------------------------------------------------------
__device__ __forceinline__ uint32_t smem_u32(const void* p) {
    uint32_t a;
    asm("{ .reg .u64 t; cvta.to.shared.u64 t, %1; cvt.u32.u64 %0, t; }" : "=r"(a) : "l"(p));
    return a;
}
#define CP_ASYNC16(dst_u32, src_ptr) \
    asm volatile("cp.async.cg.shared.global [%0], [%1], 16;" :: "r"(dst_u32), "l"(src_ptr))
#define CP_COMMIT() asm volatile("cp.async.commit_group;" ::: "memory")
#define CP_WAIT1()  asm volatile("cp.async.wait_group 1;" ::: "memory")
#define CP_WAIT0()  asm volatile("cp.async.wait_group 0;" ::: "memory")

__device__ __forceinline__ void mma16816(float* c, const uint32_t* a, const uint32_t* b) {
    asm volatile(
        "mma.sync.aligned.m16n8k16.row.col.f32.bf16.bf16.f32 "
        "{%0,%1,%2,%3}, {%4,%5,%6,%7}, {%8,%9}, {%0,%1,%2,%3};"
        : "+f"(c[0]), "+f"(c[1]), "+f"(c[2]), "+f"(c[3])
        : "r"(a[0]), "r"(a[1]), "r"(a[2]), "r"(a[3]), "r"(b[0]), "r"(b[1]));
}

__device__ __forceinline__ void ldsm_x4(uint32_t& r0, uint32_t& r1, uint32_t& r2, uint32_t& r3,
                                        uint32_t addr) {
    asm volatile("ldmatrix.sync.aligned.m8n8.x4.shared.b16 {%0,%1,%2,%3}, [%4];"
                 : "=r"(r0), "=r"(r1), "=r"(r2), "=r"(r3) : "r"(addr));
}

__device__ __forceinline__ void split_store(float4 x, uint32_t* dh, uint32_t* dl) {
    __nv_bfloat162 h0 = __floats2bfloat162_rn(x.x, x.y);
    __nv_bfloat162 h1 = __floats2bfloat162_rn(x.z, x.w);
    float l0 = x.x - __bfloat162float(h0.x);
    float l1 = x.y - __bfloat162float(h0.y);
    float l2 = x.z - __bfloat162float(h1.x);
    float l3 = x.w - __bfloat162float(h1.y);
    __nv_bfloat162 lo0 = __floats2bfloat162_rn(l0, l1);
    __nv_bfloat162 lo1 = __floats2bfloat162_rn(l2, l3);
    *(uint2*)dh = make_uint2(*(uint32_t*)&h0, *(uint32_t*)&h1);
    *(uint2*)dl = make_uint2(*(uint32_t*)&lo0, *(uint32_t*)&lo1);
}

// ---------------------------------------------------------------------------
// cp.async double-buffered tensor-core GEMM with ldmatrix fragment loads:
//   C[M,N] = alpha * A[M,K] * B[N,K]^T (+bias)
// fp32 -> bf16 (hi,lo) split via smem, 3-term compensation.
// CTA tile 128 x NTILE, K-step 32, 256 threads = 8 warps, 2 CTAs/SM.
// MODE 0: plain epilogue.
// MODE 1: epilogue writes exp(alpha*acc); row sums atomicAdd'ed into rowsum.
// MODE 2: convert phase scales A rows by rowsum (1/sum, reg-cached) and writes
//         normalized values back to AW.
// BATCH3=1: blockIdx.z selects (A,A1,A2)/(B,B1,B2), C += z*sC1.
// ---------------------------------------------------------------------------
template <int NTILE, int BATCH3, int MODE>
__global__ __launch_bounds__(256, 2) void mma_gemm(
    const float* __restrict__ A, const float* __restrict__ A1q, const float* __restrict__ A2q,
    int lda, int zdiv, long long sA1, long long sA2,
    const float* __restrict__ Bm, const float* __restrict__ B1q, const float* __restrict__ B2q,
    int ldb, long long sB1, long long sB2,
    float* __restrict__ C, int ldc, long long sC1, long long sC2,
    int K, float alpha, const float* __restrict__ bias,
    float* rowsum, float* AW)
{
    constexpr int WROW  = 20;                 // bf16 buffer: words per row (40 bf16)
    constexpr int ROWS  = 128 + NTILE;
    constexpr int NLOOP = ROWS / 32;          // 16B groups per thread per slab
    constexpr int RAWW  = ROWS * 32;          // raw fp32 slab, words
    constexpr int WM    = (NTILE == 128) ? 2 : 4;
    constexpr int MI    = 128 / (WM * 16);
    constexpr int NI    = 4;
    constexpr int AHL   = 128 * WROW;
    constexpr int BOFF  = 2 * AHL;
    constexpr int BHL   = NTILE * WROW;

    extern __shared__ char smem[];
    float*    raw0p = (float*)smem;
    float*    raw1p = (float*)(smem + RAWW * 4);
    uint32_t* bw    = (uint32_t*)(smem + 2 * RAWW * 4);
    const uint32_t raw0a = smem_u32(raw0p);
    const uint32_t raw1a = raw0a + RAWW * 4;
    const uint32_t bwa   = raw0a + 2 * RAWW * 4;

    const int z = blockIdx.z;
    if (BATCH3) {
        A  = (z == 0) ? A  : (z == 1 ? A1q : A2q);
        Bm = (z == 0) ? Bm : (z == 1 ? B1q : B2q);
        C += (long long)z * sC1;
    } else {
        const int z1 = z / zdiv, z2 = z % zdiv;
        A  += (long long)z1 * sA1 + (long long)z2 * sA2;
        Bm += (long long)z1 * sB1 + (long long)z2 * sB2;
        C  += (long long)z1 * sC1 + (long long)z2 * sC2;
        if (MODE == 2) AW += (long long)z1 * sA1 + (long long)z2 * sA2;
    }
    float* rowsumz = (MODE != 0) ? rowsum + (long long)z * TT : nullptr;

    const int m0 = blockIdx.y * 128;
    const int n0 = blockIdx.x * NTILE;

    const int tid  = threadIdx.x;
    const int warp = tid >> 5;
    const int lane = tid & 31;
    const int wm   = warp % WM;
    const int wn   = warp / WM;
    const int g    = lane >> 2;
    const int tg   = lane & 3;

    // MODE 2: cache 1/rowsum for this thread's staged A rows
    float invc[4] = {1.f, 1.f, 1.f, 1.f};
    if (MODE == 2) {
#pragma unroll
        for (int i = 0; i < 4; i++)
            invc[i] = rowsumz[m0 + (tid >> 3) + i * 32];
    }

    // ldmatrix addresses (fixed bf16 buffer)
    uint32_t a_addr[2][MI], b_addr[2][2];
    {
        const int lm  = lane & 7;
        const int l8  = (lane >> 3) & 1;
        const int l16 = lane >> 4;
        const int bm  = lane >> 3;        // matrix index 0..3 for B
#pragma unroll
        for (int kk2 = 0; kk2 < 2; kk2++) {
#pragma unroll
            for (int mi = 0; mi < MI; mi++) {
                const int row = wm * (MI * 16) + mi * 16 + lm + l8 * 8;
                const int off = kk2 * 8 + l16 * 4;
                a_addr[kk2][mi] = bwa + (uint32_t)(row * WROW + off) * 4;
            }
#pragma unroll
            for (int np = 0; np < 2; np++) {
                const int nrow = wn * 32 + np * 16 + (bm >> 1) * 8 + lm;
                const int koff = kk2 * 8 + (bm & 1) * 4;
                b_addr[kk2][np] = bwa + (uint32_t)(BOFF + nrow * WROW + koff) * 4;
            }
        }
    }

    float acc[MI][NI][4];
#pragma unroll
    for (int mi = 0; mi < MI; mi++)
#pragma unroll
        for (int ni = 0; ni < NI; ni++)
#pragma unroll
            for (int r = 0; r < 4; r++) acc[mi][ni][r] = 0.f;

    // ---- prologue: cp.async slab 0 into raw buffer 0 ----
#pragma unroll
    for (int i = 0; i < NLOOP; i++) {
        const int idx = tid + i * 256;
        const bool isA = idx < 1024;
        const int r = isA ? (idx >> 3) : ((idx - 1024) >> 3);
        const int c = (idx & 7) * 4;
        const float* src = isA ? &A[(long long)(m0 + r) * lda + c]
                               : &Bm[(long long)(n0 + r) * ldb + c];
        CP_ASYNC16(raw0a + idx * 16, src);
    }
    CP_COMMIT();

    const int NIT = K / 32;

    for (int it = 0; it < NIT; it++) {
        const bool more = (it + 1) < NIT;
        const int kbn = (it + 1) * 32;
        // ---- issue prefetch for next slab ----
        if (more) {
            const uint32_t rdst = ((it + 1) & 1) ? raw1a : raw0a;
#pragma unroll
            for (int i = 0; i < NLOOP; i++) {
                const int idx = tid + i * 256;
                const bool isA = idx < 1024;
                const int r = isA ? (idx >> 3) : ((idx - 1024) >> 3);
                const int c = (idx & 7) * 4;
                const float* src = isA ? &A[(long long)(m0 + r) * lda + kbn + c]
                                       : &Bm[(long long)(n0 + r) * ldb + kbn + c];
                CP_ASYNC16(rdst + idx * 16, src);
            }
            CP_COMMIT();
            CP_WAIT1();    // slab `it` complete (this thread's groups)
        } else {
            CP_WAIT0();
        }

        // ---- convert own groups raw -> bf16 hi/lo (+ MODE2 writeback) ----
        {
            const float* rbuf = (it & 1) ? raw1p : raw0p;
            const int kb = it * 32;
#pragma unroll
            for (int i = 0; i < NLOOP; i++) {
                const int idx = tid + i * 256;
                const bool isA = idx < 1024;
                const int r = isA ? (idx >> 3) : ((idx - 1024) >> 3);
                const int c = (idx & 7) * 4;
                float4 x = *(const float4*)(rbuf + idx * 4);
                if (MODE == 2 && isA) {
                    x.x *= invc[i]; x.y *= invc[i]; x.z *= invc[i]; x.w *= invc[i];
                    *(float4*)&AW[(long long)(m0 + r) * lda + kb + c] = x;
                }
                const uint32_t w = r * WROW + (c >> 1);
                uint32_t* dh = bw + (isA ? 0 : BOFF) + w;
                uint32_t* dl = dh + (isA ? AHL : BHL);
                split_store(x, dh, dl);
            }
        }
        __syncthreads();

        // ---- MMA from bw via ldmatrix ----
        {
#pragma unroll
            for (int kk2 = 0; kk2 < 2; kk2++) {
                uint32_t bh[NI][2], bl[NI][2];
#pragma unroll
                for (int np = 0; np < 2; np++) {
                    ldsm_x4(bh[np * 2][0], bh[np * 2][1], bh[np * 2 + 1][0], bh[np * 2 + 1][1],
                            b_addr[kk2][np]);
                    ldsm_x4(bl[np * 2][0], bl[np * 2][1], bl[np * 2 + 1][0], bl[np * 2 + 1][1],
                            b_addr[kk2][np] + BHL * 4);
                }
#pragma unroll
                for (int mi = 0; mi < MI; mi++) {
                    uint32_t ah[4], al[4];
                    ldsm_x4(ah[0], ah[1], ah[2], ah[3], a_addr[kk2][mi]);
                    ldsm_x4(al[0], al[1], al[2], al[3], a_addr[kk2][mi] + AHL * 4);
#pragma unroll
                    for (int ni = 0; ni < NI; ni++) {
                        mma16816(acc[mi][ni], ah, bh[ni]);
                        mma16816(acc[mi][ni], ah, bl[ni]);
                        mma16816(acc[mi][ni], al, bh[ni]);
                    }
                }
            }
        }
        if (more) __syncthreads();   // protect bw before next convert
    }

    // ---- epilogue ----
#pragma unroll
    for (int mi = 0; mi < MI; mi++) {
        const int r0 = m0 + wm * (MI * 16) + mi * 16 + g;
        const int r1 = r0 + 8;
        float p0 = 0.f, p1 = 0.f;
#pragma unroll
        for (int ni = 0; ni < NI; ni++) {
            const int c = n0 + wn * 32 + ni * 8 + tg * 2;
            float2 o0, o1;
            if (MODE == 1) {
                o0.x = __expf(acc[mi][ni][0] * alpha);
                o0.y = __expf(acc[mi][ni][1] * alpha);
                o1.x = __expf(acc[mi][ni][2] * alpha);
                o1.y = __expf(acc[mi][ni][3] * alpha);
                p0 += o0.x + o0.y;
                p1 += o1.x + o1.y;
            } else {
                float2 bv = make_float2(0.f, 0.f);
                if (bias) bv = *(const float2*)&bias[c];
                o0.x = acc[mi][ni][0] * alpha + bv.x;
                o0.y = acc[mi][ni][1] * alpha + bv.y;
                o1.x = acc[mi][ni][2] * alpha + bv.x;
                o1.y = acc[mi][ni][3] * alpha + bv.y;
            }
            *(float2*)&C[(long long)r0 * ldc + c] = o0;
            *(float2*)&C[(long long)r1 * ldc + c] = o1;
        }
        if (MODE == 1) {
            p0 += __shfl_xor_sync(0xffffffffu, p0, 1);
            p0 += __shfl_xor_sync(0xffffffffu, p0, 2);
            p1 += __shfl_xor_sync(0xffffffffu, p1, 1);
            p1 += __shfl_xor_sync(0xffffffffu, p1, 2);
            if (tg == 0) {
                atomicAdd(&rowsumz[r0], p0);
                atomicAdd(&rowsumz[r1], p1);
            }
        }
    }
}

// ---------------------------------------------------------------------------
// rowsum helpers
// ---------------------------------------------------------------------------
__global__ void zero_rowsum(float* rs) {
    rs[blockIdx.x * 256 + threadIdx.x] = 0.f;
}
__global__ void invert_rowsum(float* rs) {
    const int i = blockIdx.x * 256 + threadIdx.x;
    rs[i] = 1.f / rs[i];
}

// ---------------------------------------------------------------------------
// Transposes
// ---------------------------------------------------------------------------
__global__ __launch_bounds__(256) void transpose_v(const float* __restrict__ v,
                                                   float* __restrict__ vt)
{
    __shared__ float tile[32][33];
    const int z = blockIdx.z;
    const int b = z / HH, h = z % HH;
    const int m0 = blockIdx.x * 32;
    const int d0 = blockIdx.y * 32;
    const int tx = threadIdx.x & 31;
    const int ty0 = threadIdx.x >> 5;
#pragma unroll
    for (int ty = ty0; ty < 32; ty += 8)
        tile[ty][tx] = v[((long long)b * TT + m0 + ty) * EE + h * DD + d0 + tx];
    __syncthreads();
#pragma unroll
    for (int ty = ty0; ty < 32; ty += 8)
        vt[(((long long)z) * DD + d0 + ty) * TT + m0 + tx] = tile[tx][ty];
}

__global__ __launch_bounds__(256) void transpose_pk(const float* __restrict__ pk,
                                                    float* __restrict__ pkt)
{
    __shared__ float tile[32][33];
    const int k0 = blockIdx.x * 32;
    const int o0 = blockIdx.y * 32;
    const int tx = threadIdx.x & 31;
    const int ty0 = threadIdx.x >> 5;
#pragma unroll
    for (int ty = ty0; ty < 32; ty += 8)
        tile[ty][tx] = pk[(long long)(k0 + ty) * OO + o0 + tx];
    __syncthreads();
#pragma unroll
    for (int ty = ty0; ty < 32; ty += 8)
        pkt[(long long)(o0 + ty) * EE + k0 + tx] = tile[tx][ty];
}

// ---------------------------------------------------------------------------
// Launch
// ---------------------------------------------------------------------------
extern "C" void kernel_launch(void* const* d_in, const int* in_sizes, int n_in,
                              void* d_out, int out_size)
{
    const float* query = (const float*)d_in[0];
    const float* key   = (const float*)d_in[1];
    const float* value = (const float*)d_in[2];
    const float* Wq    = (const float*)d_in[3];
    const float* Wk    = (const float*)d_in[4];
    const float* Wv    = (const float*)d_in[5];
    const float* pk    = (const float*)d_in[6];
    const float* pb    = (const float*)d_in[7];

    float *qkvp, *mhp, *vtp, *pktp, *rsp, *outs, *attns;
    cudaGetSymbolAddress((void**)&qkvp,  g_qkv);
    cudaGetSymbolAddress((void**)&mhp,   g_mh);
    cudaGetSymbolAddress((void**)&vtp,   g_vt);
    cudaGetSymbolAddress((void**)&pktp,  g_pkt);
    cudaGetSymbolAddress((void**)&rsp,   g_rowsum);
    cudaGetSymbolAddress((void**)&outs,  g_out_scratch);
    cudaGetSymbolAddress((void**)&attns, g_attn_scratch);

    const long long qkvN = (long long)BB * TT * EE;
    float* qp = qkvp;
    float* kp = qkvp + qkvN;
    float* vp = qkvp + 2 * qkvN;

    const long long outN  = (long long)BB * TT * OO;
    const long long attnN = (long long)BB * HH * TT * TT;

    float* outP  = (float*)d_out;
    float* attnP;
    if ((long long)out_size >= outN + attnN) {
        attnP = outP + outN;
    } else if ((long long)out_size == attnN) {
        attnP = (float*)d_out;
        outP  = outs;
    } else {
        attnP = attns;
    }

    // smem: 2 raw fp32 slabs + 1 bf16 hi/lo buffer
    constexpr int SMEM128 = (2 * 256 * 32 + 256 * 40) * 4;  // 106496
    constexpr int SMEM64  = (2 * 192 * 32 + 192 * 40) * 4;  // 79872
    cudaFuncSetAttribute(mma_gemm<128, 1, 0>, cudaFuncAttributeMaxDynamicSharedMemorySize, SMEM128);
    cudaFuncSetAttribute(mma_gemm<128, 0, 0>, cudaFuncAttributeMaxDynamicSharedMemorySize, SMEM128);
    cudaFuncSetAttribute(mma_gemm<128, 0, 1>, cudaFuncAttributeMaxDynamicSharedMemorySize, SMEM128);
    cudaFuncSetAttribute(mma_gemm<64, 0, 2>,  cudaFuncAttributeMaxDynamicSharedMemorySize, SMEM64);

    // 0) zero row sums (graph-replay safe)
    zero_rowsum<<<(BB * HH * TT) / 256, 256>>>(rsp);

    // 1) Q/K/V projections, batched over z = 0,1,2
    {
        dim3 grid(EE / 128, (BB * TT) / 128, 3);
        mma_gemm<128, 1, 0><<<grid, 256, SMEM128>>>(
            query, key, value, EE, 1, 0, 0,
            Wq, Wk, Wv, EE, 0, 0,
            qkvp, EE, qkvN, 0,
            EE, 1.f, nullptr, nullptr, nullptr);
    }

    // transposes: V -> [b][h][d][m], pk -> [o][k]
    {
        dim3 gv(TT / 32, DD / 32, BB * HH);
        transpose_v<<<gv, 256>>>(vp, vtp);
        dim3 gp(EE / 32, OO / 32, 1);
        transpose_pk<<<gp, 256>>>(pk, pktp);
    }

    // 2) attn = exp(0.125 * q @ k^T), row sums via atomics
    {
        dim3 grid(TT / 128, TT / 128, BB * HH);
        mma_gemm<128, 0, 1><<<grid, 256, SMEM128>>>(
            qp, nullptr, nullptr, EE, HH, (long long)TT * EE, DD,
            kp, nullptr, nullptr, EE,     (long long)TT * EE, DD,
            attnP, TT, (long long)HH * TT * TT, (long long)TT * TT,
            DD, 0.125f, nullptr, rsp, nullptr);
    }

    // 3) invert row sums
    invert_rowsum<<<(BB * HH * TT) / 256, 256>>>(rsp);

    // 4) mh = softmax(attn) @ vT^T ; normalizes attn in staging + writes it back
    {
        dim3 grid(1, TT / 128, BB * HH);
        mma_gemm<64, 0, 2><<<grid, 256, SMEM64>>>(
            attnP, nullptr, nullptr, TT, HH, (long long)HH * TT * TT, (long long)TT * TT,
            vtp, nullptr, nullptr, TT, (long long)HH * DD * TT, (long long)DD * TT,
            mhp, EE, (long long)TT * EE, DD,
            TT, 1.f, nullptr, rsp, attnP);
    }

    // 5) out = mh @ pkT^T + bias
    {
        dim3 grid(OO / 128, (BB * TT) / 128, 1);
        mma_gemm<128, 0, 0><<<grid, 256, SMEM128>>>(
            mhp, nullptr, nullptr, EE, 1, 0, 0,
            pktp, nullptr, nullptr, EE, 0, 0,
            outP, OO, 0, 0, EE, 1.f, pb, nullptr, nullptr);
    }
}